// round 8
// baseline (speedup 1.0000x reference)
#include <cuda_runtime.h>
#include <cuda_bf16.h>
#include <math_constants.h>

// Problem constants (fixed by the reference)
#define BB     2
#define HH     112
#define WW     112
#define HW     (HH * WW)        // 12544
#define NPIX   (BB * HW)        // 25088
#define SEG_T  0.7f
#define EPS_K  1e-7f
// Output nonzero requires q <= eps - ln(0.7) = 0.3566750.
// Radius bound uses 0.36 (margin), store cutoff 0.37 (margin).
#define Q_RAD  0.36f
#define Q_CUT  0.37f

// Tiling: 7x7 tiles of 16x16 per batch image; 98 blocks total, 256 thr each.
#define TILE   16
#define TPB    (TILE * TILE)     // 256 threads
#define TPS    7                 // tiles per side
#define HALO   8                 // covers R<=8 <=> maxvar<=88.9 <=> |v|<=9.43
#define REG    (TILE + 2 * HALO) // 32: source region side
#define RPTS   (REG * REG)       // 1024 source points = 4 per thread

// ---------------------------------------------------------------------------
// One kernel, no grid sync, no global atomics, no global scratch:
//  1. init smem qmin tile to +inf
//  2. each thread evaluates 4 source points from tile+halo; selected points
//     scatter their quadratic q into the smem tile via atomicMin (boxes
//     clipped to the tile; q>=0 so uint ordering == float ordering)
//  3. __syncthreads, then per-pixel exp(-qmin+eps) + 0.7 threshold -> gmem
// ---------------------------------------------------------------------------
__global__ void __launch_bounds__(TPB, 1)
k_tiled(const float* __restrict__ variance,
        const float* __restrict__ center,
        float* __restrict__ out, int out_size)
{
    __shared__ unsigned int qmin[TPB];

    const int tid = threadIdx.x;
    qmin[tid] = 0x7F800000u;   // +inf

    const int blk = blockIdx.x;
    const int b   = blk / (TPS * TPS);
    const int t   = blk - b * (TPS * TPS);
    const int tr  = (t / TPS) * TILE;   // tile origin row
    const int tc  = (t % TPS) * TILE;   // tile origin col

    __syncthreads();

    const float* varb = variance + (size_t)b * 3 * HW;
    const float* cenb = center   + (size_t)b * HW;

    #pragma unroll
    for (int pp = 0; pp < RPTS / TPB; ++pp) {
        int p  = tid + pp * TPB;
        int lr = p >> 5;            // p / REG  (REG = 32)
        int lc = p & (REG - 1);     // p % REG
        int pr = tr - HALO + lr;
        int pc = tc - HALO + lc;
        if (pr < 0 || pr >= HH || pc < 0 || pc >= WW) continue;

        int   pix  = pr * WW + pc;
        float mask = (cenb[pix] > SEG_T) ? 1.0f : 0.0f;
        float vx   = varb[pix]      * mask;
        float vy   = varb[HW + pix] * mask;
        // sel = (vx + vy) != 0  (matches torch.nonzero(vx+vy) semantics)
        if ((vx + vy) == 0.0f) continue;

        float v2    = varb[2 * HW + pix];
        float theta = 3.14f * (1.0f / (1.0f + expf(-v2)));
        float s, c;
        sincosf(theta, &s, &c);

        float var_x = vx * vx + EPS_K;
        float var_y = vy * vy + EPS_K;

        float inv2x = 1.0f / (2.0f * var_x);
        float inv2y = 1.0f / (2.0f * var_y);

        // a = cos^2/(2vx) + sin^2/(2vy);  c = sin^2/(2vx) + cos^2/(2vy)
        float A  = c * c * inv2x + s * s * inv2y;
        float C  = s * s * inv2x + c * c * inv2y;
        // ref: b = -2sc/(4vx) + 2sc/(4vy); cross coefficient is 2*b
        float B2 = 2.0f * (-2.0f * s * c / (4.0f * var_x)
                           + 2.0f * s * c / (4.0f * var_y));

        // Pruning radius: q >= d^2/(2*max(var_x,var_y)); nonzero output needs
        // q <= 0.3567, so d^2 <= 2*maxvar*0.3567. (R <= HALO for any sane v.)
        float maxvar = fmaxf(var_x, var_y);
        int R = (int)floorf(sqrtf(2.0f * maxvar * Q_RAD)) + 1;

        // Box clipped to THIS tile (empty -> loops skip naturally).
        int i0 = max(tr, pr - R), i1 = min(tr + TILE - 1, pr + R);
        int j0 = max(tc, pc - R), j1 = min(tc + TILE - 1, pc + R);

        for (int i = i0; i <= i1; ++i) {
            float di  = (float)(i - pr);
            float adi = A * di * di;
            float bdi = B2 * di;
            int   row = (i - tr) * TILE - tc;
            for (int j = j0; j <= j1; ++j) {
                float dj = (float)(j - pc);
                float q  = fmaf(C * dj + bdi, dj, adi);
                if (q <= Q_CUT) {
                    atomicMin(&qmin[row + j], __float_as_uint(q));
                }
            }
        }
    }

    __syncthreads();

    // ---- finalize this tile's pixel ----
    {
        int oy = tid >> 4;          // tid / TILE
        int ox = tid & (TILE - 1);  // tid % TILE
        float q = __uint_as_float(qmin[tid]);
        float g = expf(-q + EPS_K);            // q=+inf -> g=0
        out[(size_t)b * HW + (tr + oy) * WW + (tc + ox)] =
            (g >= 0.7f) ? g : 0.0f;
    }

    // Zero-fill any trailing output elements (the `flag` scalar).
    if (blk == 0 && tid == 0) {
        for (int o = NPIX; o < out_size; ++o) out[o] = 0.0f;
    }
}

// ---------------------------------------------------------------------------
// Inputs (metadata order): x[2,32,112,112], variance[2,3,112,112],
// center_map[2,1,112,112], conv_w[1,32], conv_b[1].
// x / conv_w / conv_b are dead in the reference (threshold branch unused).
// ---------------------------------------------------------------------------
extern "C" void kernel_launch(void* const* d_in, const int* in_sizes, int n_in,
                              void* d_out, int out_size)
{
    const float* variance = (const float*)d_in[1];
    const float* center   = (const float*)d_in[2];
    float*       out      = (float*)d_out;

    k_tiled<<<BB * TPS * TPS, TPB>>>(variance, center, out, out_size);
}

// round 10
// speedup vs baseline: 2.2762x; 2.2762x over previous
#include <cuda_runtime.h>
#include <cuda_bf16.h>
#include <math_constants.h>

// Problem constants (fixed by the reference)
#define BB     2
#define HH     112
#define WW     112
#define HW     (HH * WW)        // 12544
#define NPIX   (BB * HW)        // 25088
#define SEG_T  0.7f
#define EPS_K  1e-7f
// Output nonzero requires q <= eps - ln(0.7) = 0.3566750.
#define Q_RAD  0.36f
#define Q_CUT  0.37f

// 7x7 tiles of 16x16 per image; 98 blocks; 1024 threads = one per region pt.
#define TILE   16
#define TPS    7
#define HALO   8                 // R<=8 <=> maxvar<=88.9 <=> |v|<=9.43
#define REG    32                // TILE + 2*HALO
#define NTHR   1024              // REG*REG region points, 1 per thread

__global__ void __launch_bounds__(NTHR, 1)
k_one(const float* __restrict__ variance,
      const float* __restrict__ center,
      float* __restrict__ out, int out_size)
{
    __shared__ unsigned int qmin[TILE * TILE];
    __shared__ float wl_vx[NTHR], wl_vy[NTHR], wl_v2[NTHR];
    __shared__ int   wl_pr[NTHR], wl_pc[NTHR];   // tile-local point coords
    __shared__ int   wl_cnt;

    const int tid = threadIdx.x;
    if (tid < TILE * TILE) qmin[tid] = 0x7F800000u;   // +inf
    if (tid == 0) wl_cnt = 0;

    const int blk = blockIdx.x;
    const int b   = blk / (TPS * TPS);
    const int t   = blk - b * (TPS * TPS);
    const int tr  = (t / TPS) * TILE;
    const int tc  = (t % TPS) * TILE;

    const float* varb = variance + (size_t)b * 3 * HW;
    const float* cenb = center   + (size_t)b * HW;

    // ---- Phase A: one region point per thread; 4 independent loads up front.
    // warp id == region row (tid>>5), so row bounds are warp-uniform.
    const int lr = tid >> 5;
    const int lc = tid & 31;
    const int pr = tr - HALO + lr;
    const int pc = tc - HALO + lc;
    const bool inb = (pr >= 0) & (pr < HH) & (pc >= 0) & (pc < WW);

    float vx = 0.0f, vy = 0.0f, v2 = 0.0f;
    if (inb) {
        int pix = pr * WW + pc;
        float cm  = cenb[pix];
        float a0  = varb[pix];
        float a1  = varb[HW + pix];
        float a2  = varb[2 * HW + pix];
        float mask = (cm > SEG_T) ? 1.0f : 0.0f;
        vx = a0 * mask;
        vy = a1 * mask;
        v2 = a2;
    }
    // sel = (vx + vy) != 0  (matches torch.nonzero(vx+vy) semantics)
    const bool sel = inb && ((vx + vy) != 0.0f);

    __syncthreads();   // qmin + wl_cnt initialized before push/scatter

    // ---- Phase B: warp-aggregated compaction of selected points.
    {
        unsigned m = __ballot_sync(0xFFFFFFFFu, sel);
        if (m) {
            int lane   = tid & 31;
            int leader = __ffs(m) - 1;
            int base   = 0;
            if (lane == leader) base = atomicAdd(&wl_cnt, __popc(m));
            base = __shfl_sync(0xFFFFFFFFu, base, leader);
            if (sel) {
                int slot = base + __popc(m & ((1u << lane) - 1u));
                wl_vx[slot] = vx;
                wl_vy[slot] = vy;
                wl_v2[slot] = v2;
                wl_pr[slot] = pr - tr;   // tile-local (range [-8, 23])
                wl_pc[slot] = pc - tc;
            }
        }
    }
    __syncthreads();
    const int cnt = wl_cnt;

    // ---- Phase C: dense coefficient math + scatter (threads < cnt active,
    // fully-packed warps). Math order identical to the validated R2 kernel.
    if (tid < cnt) {
        float pvx = wl_vx[tid], pvy = wl_vy[tid], pv2 = wl_v2[tid];
        int   lpr = wl_pr[tid], lpc = wl_pc[tid];

        float theta = 3.14f * (1.0f / (1.0f + expf(-pv2)));
        float s, c;
        sincosf(theta, &s, &c);

        float var_x = pvx * pvx + EPS_K;
        float var_y = pvy * pvy + EPS_K;

        float inv2x = 1.0f / (2.0f * var_x);
        float inv2y = 1.0f / (2.0f * var_y);

        float A  = c * c * inv2x + s * s * inv2y;
        float C  = s * s * inv2x + c * c * inv2y;
        float B2 = 2.0f * (-2.0f * s * c / (4.0f * var_x)
                           + 2.0f * s * c / (4.0f * var_y));

        // q >= d^2/(2*maxvar): nonzero output needs q <= 0.3567
        float maxvar = fmaxf(var_x, var_y);
        int R = (int)floorf(sqrtf(2.0f * maxvar * Q_RAD)) + 1;   // <= HALO

        int i0 = max(0, lpr - R), i1 = min(TILE - 1, lpr + R);
        int j0 = max(0, lpc - R), j1 = min(TILE - 1, lpc + R);

        for (int i = i0; i <= i1; ++i) {
            float di  = (float)(i - lpr);
            float adi = A * di * di;
            float bdi = B2 * di;
            int   row = i * TILE;
            for (int j = j0; j <= j1; ++j) {
                float dj = (float)(j - lpc);
                float q  = fmaf(C * dj + bdi, dj, adi);
                if (q <= Q_CUT) {
                    unsigned qb = __float_as_uint(q);
                    // read-check cuts useless atomics ~3x; races benign
                    if (qb < qmin[row + j])
                        atomicMin(&qmin[row + j], qb);
                }
            }
        }
    }

    __syncthreads();

    // ---- Phase D: finalize this tile (threads 0..255 own one pixel each).
    if (tid < TILE * TILE) {
        int oy = tid >> 4;
        int ox = tid & (TILE - 1);
        float q = __uint_as_float(qmin[tid]);
        float g = expf(-q + EPS_K);            // q=+inf -> g=0
        out[(size_t)b * HW + (tr + oy) * WW + (tc + ox)] =
            (g >= 0.7f) ? g : 0.0f;
    }

    // Zero-fill any trailing output elements (the `flag` scalar).
    if (blk == 0 && tid == 0) {
        for (int o = NPIX; o < out_size; ++o) out[o] = 0.0f;
    }
}

// ---------------------------------------------------------------------------
// Inputs (metadata order): x[2,32,112,112], variance[2,3,112,112],
// center_map[2,1,112,112], conv_w[1,32], conv_b[1].
// x / conv_w / conv_b are dead in the reference (threshold branch unused).
// ---------------------------------------------------------------------------
extern "C" void kernel_launch(void* const* d_in, const int* in_sizes, int n_in,
                              void* d_out, int out_size)
{
    const float* variance = (const float*)d_in[1];
    const float* center   = (const float*)d_in[2];
    float*       out      = (float*)d_out;

    k_one<<<BB * TPS * TPS, NTHR>>>(variance, center, out, out_size);
}